// round 10
// baseline (speedup 1.0000x reference)
#include <cuda_runtime.h>
#include <cuda_bf16.h>
#include <mma.h>
#include <math.h>
#include <stdint.h>

using namespace nvcuda;

#define NMAX 65536
#define HD   128
#define LDB  136    // bf16 smem leading dim (elements)
#define LDBF 132    // f32 bias tile leading dim (elements, mult of 4)

typedef unsigned long long u64;

// ----- scratch -----
__device__ float g_agg1[NMAX * 32];
__device__ float g_h   [NMAX * HD];
__device__ float g_agg2[NMAX * HD];
__device__ float g_h2  [NMAX * HD];
__device__ float g_t1  [NMAX * HD];
__device__ float g_pooled[64 * HD];
__device__ __nv_bfloat16 g_whi[5 * 128 * 128];
__device__ __nv_bfloat16 g_wlo[5 * 128 * 128];

__device__ __forceinline__ float leakyf(float v) { return v > 0.f ? v : 0.01f * v; }

__device__ __forceinline__ u64 pack2(float lo, float hi) {
    u64 r; asm("mov.b64 %0, {%1, %2};" : "=l"(r) : "f"(lo), "f"(hi)); return r;
}
__device__ __forceinline__ void unpack2(float& lo, float& hi, u64 v) {
    asm("mov.b64 {%0, %1}, %2;" : "=f"(lo), "=f"(hi) : "l"(v));
}
__device__ __forceinline__ u64 fma2(u64 a, u64 b, u64 c) {
    u64 d; asm("fma.rn.f32x2 %0, %1, %2, %3;" : "=l"(d) : "l"(a), "l"(b), "l"(c)); return d;
}

// ---------------------------------------------------------------------------
// Combined weight split for all 5 matrices (ONE launch): grid (64, 5)
// ---------------------------------------------------------------------------
__global__ void wsplit_all(const float* __restrict__ w0, const float* __restrict__ w1,
                           const float* __restrict__ w2, const float* __restrict__ w3,
                           const float* __restrict__ w4,
                           __nv_bfloat16* __restrict__ Whi, __nv_bfloat16* __restrict__ Wlo)
{
    int m = blockIdx.y;
    const float* W = (m == 0) ? w0 : (m == 1) ? w1 : (m == 2) ? w2 : (m == 3) ? w3 : w4;
    int i = blockIdx.x * 256 + threadIdx.x;
    float v = W[i];
    __nv_bfloat16 h = __float2bfloat16(v);
    Whi[m * 16384 + i] = h;
    Wlo[m * 16384 + i] = __float2bfloat16(v - __bfloat162float(h));
}

// ---------------------------------------------------------------------------
// bf16x3 wmma GEMM, 64-row tiles, direct-to-global epilogue.
// acc initialized from replicated bias tile; activation applied elementwise
// on fragment registers; store_matrix_sync straight to Out.
// ---------------------------------------------------------------------------
template<int ACT, bool ADD>
__global__ __launch_bounds__(256)
void wmma_gemm(const float* __restrict__ In, const float* __restrict__ In2,
               const __nv_bfloat16* __restrict__ Whi, const __nv_bfloat16* __restrict__ Wlo,
               const float* __restrict__ bias, float* __restrict__ Out)
{
    extern __shared__ __align__(256) char sm[];
    __nv_bfloat16* aHi = (__nv_bfloat16*)sm;            // 64*136*2  = 17408 B
    __nv_bfloat16* aLo = aHi + 64 * LDB;                // 17408 B
    __nv_bfloat16* bHi = aLo + 64 * LDB;                // 128*136*2 = 34816 B
    __nv_bfloat16* bLo = bHi + 128 * LDB;               // 34816 B
    float* sBias = (float*)(bLo + 128 * LDB);           // 16*132*4  = 8448 B

    int tid = threadIdx.x;
    int row0 = blockIdx.x * 64;

    // ---- bias tile: 16 identical rows of bias[0..127]
    for (int i = tid; i < 16 * LDBF; i += 256) {
        int c = i % LDBF;
        sBias[i] = (c < 128) ? bias[c] : 0.f;
    }

    // ---- convert A: thread -> row r=tid/4 (0..63), cols (tid&3)*32..+31
    {
        int r = tid >> 2, c0 = (tid & 3) * 32;
        const float4* arow  = (const float4*)(In  + (size_t)(row0 + r) * 128 + c0);
        const float4* a2row = (const float4*)(In2 + (size_t)(row0 + r) * 128 + c0);
        #pragma unroll
        for (int j = 0; j < 8; j++) {
            float4 v = arow[j];
            if (ADD) {
                float4 u = a2row[j];
                v.x += u.x; v.y += u.y; v.z += u.z; v.w += u.w;
            }
            float f[4] = {v.x, v.y, v.z, v.w};
            uint2 hi, lo;
            {
                __nv_bfloat16 h0 = __float2bfloat16(f[0]), h1 = __float2bfloat16(f[1]);
                __nv_bfloat16 h2 = __float2bfloat16(f[2]), h3 = __float2bfloat16(f[3]);
                hi.x = (uint32_t)__bfloat16_as_ushort(h0) | ((uint32_t)__bfloat16_as_ushort(h1) << 16);
                hi.y = (uint32_t)__bfloat16_as_ushort(h2) | ((uint32_t)__bfloat16_as_ushort(h3) << 16);
                __nv_bfloat16 l0 = __float2bfloat16(f[0] - __bfloat162float(h0));
                __nv_bfloat16 l1 = __float2bfloat16(f[1] - __bfloat162float(h1));
                __nv_bfloat16 l2 = __float2bfloat16(f[2] - __bfloat162float(h2));
                __nv_bfloat16 l3 = __float2bfloat16(f[3] - __bfloat162float(h3));
                lo.x = (uint32_t)__bfloat16_as_ushort(l0) | ((uint32_t)__bfloat16_as_ushort(l1) << 16);
                lo.y = (uint32_t)__bfloat16_as_ushort(l2) | ((uint32_t)__bfloat16_as_ushort(l3) << 16);
            }
            *(uint2*)(aHi + r * LDB + c0 + j * 4) = hi;
            *(uint2*)(aLo + r * LDB + c0 + j * 4) = lo;
        }
    }
    // ---- load pre-split W: 2048 uint4 each
    #pragma unroll
    for (int it = 0; it < 8; it++) {
        int i = it * 256 + tid;
        int rw = i >> 4, cw = (i & 15) * 8;
        *(uint4*)(bHi + rw * LDB + cw) = ((const uint4*)Whi)[i];
        *(uint4*)(bLo + rw * LDB + cw) = ((const uint4*)Wlo)[i];
    }
    __syncthreads();

    // ---- MMA
    int wid = tid >> 5;
    int strip = wid & 3;        // 16-row strip within 64 rows
    int chalf = wid >> 2;       // 64-col half
    wmma::fragment<wmma::accumulator, 16, 16, 16, float> acc[4];
    #pragma unroll
    for (int nt = 0; nt < 4; nt++)
        wmma::load_matrix_sync(acc[nt], sBias + chalf * 64 + nt * 16, LDBF, wmma::mem_row_major);

    const __nv_bfloat16* apH = aHi + strip * 16 * LDB;
    const __nv_bfloat16* apL = aLo + strip * 16 * LDB;
    const __nv_bfloat16* bpH = bHi + chalf * 64;
    const __nv_bfloat16* bpL = bLo + chalf * 64;

    // passes 1+2 share Bhi
    #pragma unroll
    for (int k = 0; k < 8; k++) {
        wmma::fragment<wmma::matrix_a, 16, 16, 16, __nv_bfloat16, wmma::row_major> afH, afL;
        wmma::load_matrix_sync(afH, apH + k * 16, LDB);
        wmma::load_matrix_sync(afL, apL + k * 16, LDB);
        #pragma unroll
        for (int nt = 0; nt < 4; nt++) {
            wmma::fragment<wmma::matrix_b, 16, 16, 16, __nv_bfloat16, wmma::row_major> bf;
            wmma::load_matrix_sync(bf, bpH + k * 16 * LDB + nt * 16, LDB);
            wmma::mma_sync(acc[nt], afH, bf, acc[nt]);
            wmma::mma_sync(acc[nt], afL, bf, acc[nt]);
        }
    }
    // pass 3: Ahi * Blo
    #pragma unroll
    for (int k = 0; k < 8; k++) {
        wmma::fragment<wmma::matrix_a, 16, 16, 16, __nv_bfloat16, wmma::row_major> afH;
        wmma::load_matrix_sync(afH, apH + k * 16, LDB);
        #pragma unroll
        for (int nt = 0; nt < 4; nt++) {
            wmma::fragment<wmma::matrix_b, 16, 16, 16, __nv_bfloat16, wmma::row_major> bf;
            wmma::load_matrix_sync(bf, bpL + k * 16 * LDB + nt * 16, LDB);
            wmma::mma_sync(acc[nt], afH, bf, acc[nt]);
        }
    }

    // ---- direct epilogue: elementwise activation on fragments, store to global
    float* obase = Out + (size_t)(row0 + strip * 16) * 128 + chalf * 64;
    #pragma unroll
    for (int nt = 0; nt < 4; nt++) {
        #pragma unroll
        for (int i = 0; i < acc[nt].num_elements; i++) {
            float v = acc[nt].x[i];
            acc[nt].x[i] = (ACT == 0) ? leakyf(v) : fmaxf(v, 0.f);
        }
        wmma::store_matrix_sync(obase + nt * 16, acc[nt], 128, wmma::mem_row_major);
    }
}

// ---------------------------------------------------------------------------
// Edge layer 1 (R5, unchanged)
// ---------------------------------------------------------------------------
#define E1_CHUNK 32
__global__ __launch_bounds__(256)
void edge1_kernel(const float* __restrict__ x, const int* __restrict__ src,
                  const int* __restrict__ dst, const float* __restrict__ ea,
                  const float* __restrict__ W, const float* __restrict__ bias,
                  float* __restrict__ agg, int E)
{
    int lane = threadIdx.x & 31;
    int warp = blockIdx.x * 8 + (threadIdx.x >> 5);
    int base = warp * E1_CHUNK;
    if (base >= E) return;

    float w[16];
    #pragma unroll
    for (int k = 0; k < 16; k++) w[k] = __ldg(&W[k * 32 + lane]);
    float b = __ldg(&bias[lane]);

    int sA = __ldg(&src[base + lane]);
    int sD = __ldg(&dst[base + lane]);

    #pragma unroll 4
    for (int i = 0; i < E1_CHUNK; i++) {
        int e = base + i;
        int s = __shfl_sync(0xffffffffu, sA, i);
        int d = __shfl_sync(0xffffffffu, sD, i);
        float av = (lane < 16) ? __ldg(&ea[(size_t)e * 16 + lane]) : 0.f;
        float g = __ldg(&x[(size_t)s * 32 + lane]);
        float t = b;
        #pragma unroll
        for (int k = 0; k < 16; k++)
            t = fmaf(__shfl_sync(0xffffffffu, av, k), w[k], t);
        float m = fmaxf(t + g, 0.f);
        asm volatile("red.global.add.f32 [%0], %1;"
                     :: "l"(agg + (size_t)d * 32 + lane), "f"(m) : "memory");
    }
}

// ---------------------------------------------------------------------------
// Edge layer 2 (R5, unchanged): two warps / 16-edge chunk, 64 ch per warp
// ---------------------------------------------------------------------------
#define E2_CHUNK 16
__global__ __launch_bounds__(256, 4)
void edge2_kernel(const float* __restrict__ h, const int* __restrict__ src,
                  const int* __restrict__ dst, const float* __restrict__ ea,
                  const float* __restrict__ W, const float* __restrict__ bias,
                  float* __restrict__ agg, int E)
{
    int lane = threadIdx.x & 31;
    int warp = blockIdx.x * 8 + (threadIdx.x >> 5);
    int chunk = warp >> 1;
    int half  = warp & 1;
    int base = chunk * E2_CHUNK;
    if (base >= E) return;
    int ch = half * 64 + lane * 2;

    u64 w2[16];
    #pragma unroll
    for (int k = 0; k < 16; k++) {
        float2 wv = *(const float2*)(W + (size_t)k * 128 + ch);
        w2[k] = pack2(wv.x, wv.y);
    }
    float2 bv = *(const float2*)(bias + ch);
    u64 b2 = pack2(bv.x, bv.y);

    int li = lane & 15;
    int sd = (lane < 16) ? __ldg(&src[base + li]) : __ldg(&dst[base + li]);

    for (int i = 0; i < E2_CHUNK; i++) {
        int e = base + i;
        int s = __shfl_sync(0xffffffffu, sd, i);
        int d = __shfl_sync(0xffffffffu, sd, 16 + i);
        float av = (lane < 16) ? __ldg(&ea[(size_t)e * 16 + lane]) : 0.f;
        float2 g = *(const float2*)(h + (size_t)s * HD + ch);

        u64 tE = b2, tO = 0ull;
        #pragma unroll
        for (int k = 0; k < 16; k += 2) {
            float a0 = __shfl_sync(0xffffffffu, av, k);
            float a1 = __shfl_sync(0xffffffffu, av, k + 1);
            tE = fma2(pack2(a0, a0), w2[k],     tE);
            tO = fma2(pack2(a1, a1), w2[k + 1], tO);
        }
        float tx, ty, ux, uy;
        unpack2(tx, ty, tE);
        unpack2(ux, uy, tO);
        float mx = fmaxf(tx + ux + g.x, 0.f);
        float my = fmaxf(ty + uy + g.y, 0.f);
        asm volatile("red.global.add.v2.f32 [%0], {%1,%2};"
                     :: "l"(agg + (size_t)d * HD + ch), "f"(mx), "f"(my) : "memory");
    }
}

// ---------------------------------------------------------------------------
// FFMA GEMM for the K=32 layer (unchanged)
// ---------------------------------------------------------------------------
template<int K, int ACT, bool ADD>
__global__ __launch_bounds__(256)
void gemm_kernel(const float* __restrict__ In, const float* __restrict__ In2,
                 const float* __restrict__ W, const float* __restrict__ bias,
                 float* __restrict__ Out)
{
    __shared__ float sIn[64 * K];
    __shared__ float sW[16 * 128];
    int tid = threadIdx.x;
    int row0 = blockIdx.x * 64;

    const float4* inp  = (const float4*)(In  + (size_t)row0 * K);
    const float4* inp2 = (const float4*)(In2 + (size_t)row0 * K);
    for (int i = tid; i < (64 * K) / 4; i += 256) {
        float4 v = inp[i];
        if (ADD) {
            float4 u = inp2[i];
            v.x += u.x; v.y += u.y; v.z += u.z; v.w += u.w;
        }
        ((float4*)sIn)[i] = v;
    }

    int cx = tid & 31;
    int ry = tid >> 5;
    float4 b4 = ((const float4*)bias)[cx];
    float4 acc[8];
    #pragma unroll
    for (int m = 0; m < 8; m++) acc[m] = b4;

    for (int kc = 0; kc < K; kc += 16) {
        __syncthreads();
        for (int i = tid; i < (16 * 128) / 4; i += 256)
            ((float4*)sW)[i] = ((const float4*)(W + (size_t)kc * 128))[i];
        __syncthreads();
        #pragma unroll
        for (int k = 0; k < 16; k++) {
            float4 w = ((float4*)sW)[k * 32 + cx];
            #pragma unroll
            for (int m = 0; m < 8; m++) {
                float a = sIn[(ry * 8 + m) * K + (kc + k)];
                acc[m].x += a * w.x; acc[m].y += a * w.y;
                acc[m].z += a * w.z; acc[m].w += a * w.w;
            }
        }
    }

    #pragma unroll
    for (int m = 0; m < 8; m++) {
        float4 v = acc[m];
        if (ACT == 0) {
            v.x = leakyf(v.x); v.y = leakyf(v.y); v.z = leakyf(v.z); v.w = leakyf(v.w);
        } else {
            v.x = fmaxf(v.x, 0.f); v.y = fmaxf(v.y, 0.f);
            v.z = fmaxf(v.z, 0.f); v.w = fmaxf(v.w, 0.f);
        }
        *(float4*)(Out + (size_t)(row0 + ry * 8 + m) * 128 + cx * 4) = v;
    }
}

// ---------------------------------------------------------------------------
__global__ void pool_kernel(const float* __restrict__ h2, float* __restrict__ pooled, int Nper)
{
    int b = blockIdx.x;
    int tid = threadIdx.x;
    int c = tid & 127, half = tid >> 7;
    float s = 0.f;
    const float* base = h2 + (size_t)b * Nper * HD + c;
    for (int i = half; i < Nper; i += 2) s += base[(size_t)i * HD];
    __shared__ float sm[256];
    sm[tid] = s;
    __syncthreads();
    if (half == 0) pooled[b * HD + c] = (sm[c] + sm[128 + c]) / (float)Nper;
}

__global__ void action_kernel(const float* __restrict__ pooled,
                              const float* __restrict__ w1, const float* __restrict__ b1,
                              const float* __restrict__ w2, const float* __restrict__ b2,
                              float* __restrict__ out)
{
    __shared__ float sp[128], s1[128], s2[10];
    int b = blockIdx.x;
    int tid = threadIdx.x;
    sp[tid] = pooled[b * 128 + tid];
    __syncthreads();
    float acc = b1[tid];
    #pragma unroll 8
    for (int k = 0; k < 128; k++) acc += sp[k] * w1[k * 128 + tid];
    s1[tid] = leakyf(acc);
    __syncthreads();
    if (tid < 10) {
        float a2 = b2[tid];
        #pragma unroll 8
        for (int k = 0; k < 128; k++) a2 += s1[k] * w2[k * 10 + tid];
        s2[tid] = leakyf(a2);
    }
    __syncthreads();
    if (tid == 0) {
        float mx = -1e30f;
        for (int j = 0; j < 10; j++) mx = fmaxf(mx, s2[j]);
        float ex[10], sum = 0.f;
        for (int j = 0; j < 10; j++) { ex[j] = expf(s2[j] - mx); sum += ex[j]; }
        float inv = 1.f / sum;
        for (int j = 0; j < 10; j++) out[b * 10 + j] = ex[j] * inv;
    }
}

__global__ void score_kernel(const float* __restrict__ nh, const float* __restrict__ w3,
                             const float* __restrict__ b3, float* __restrict__ out,
                             int N, int Nper)
{
    int r = blockIdx.x * 8 + (threadIdx.x >> 5);
    int lane = threadIdx.x & 31;
    if (r >= N) return;
    float4 v = *(const float4*)(nh + (size_t)r * HD + lane * 4);
    float4 w = *(const float4*)(w3 + lane * 4);
    float acc = v.x * w.x + v.y * w.y + v.z * w.z + v.w * w.w;
    #pragma unroll
    for (int o = 16; o; o >>= 1) acc += __shfl_xor_sync(0xffffffffu, acc, o);
    if (lane == 0) {
        float z = acc + b3[0];
        out[(size_t)(r & 63) * Nper + (r >> 6)] = 1.f / (1.f + expf(-z));
    }
}

// ---------------------------------------------------------------------------
extern "C" void kernel_launch(void* const* d_in, const int* in_sizes, int n_in,
                              void* d_out, int out_size)
{
    const float* x     = (const float*)d_in[0];
    const int*   ei    = (const int*)  d_in[1];
    const float* ea    = (const float*)d_in[2];
    const float* e1_w  = (const float*)d_in[3];
    const float* e1_b  = (const float*)d_in[4];
    const float* c1_w1 = (const float*)d_in[5];
    const float* c1_b1 = (const float*)d_in[6];
    const float* c1_w2 = (const float*)d_in[7];
    const float* c1_b2 = (const float*)d_in[8];
    const float* e2_w  = (const float*)d_in[9];
    const float* e2_b  = (const float*)d_in[10];
    const float* c2_w1 = (const float*)d_in[11];
    const float* c2_b1 = (const float*)d_in[12];
    const float* c2_w2 = (const float*)d_in[13];
    const float* c2_b2 = (const float*)d_in[14];
    const float* a_w1  = (const float*)d_in[15];
    const float* a_b1  = (const float*)d_in[16];
    const float* a_w2  = (const float*)d_in[17];
    const float* a_b2  = (const float*)d_in[18];
    const float* n_w1  = (const float*)d_in[19];
    const float* n_b1  = (const float*)d_in[20];
    const float* n_w2  = (const float*)d_in[21];
    const float* n_b2  = (const float*)d_in[22];
    const float* n_w3  = (const float*)d_in[23];
    const float* n_b3  = (const float*)d_in[24];

    int N = in_sizes[0] / 32;
    int E = in_sizes[1] / 2;
    int Nper = N / 64;
    const int* src = ei;
    const int* dst = ei + E;

    float *agg1, *h, *agg2, *h2, *t1, *pooled;
    __nv_bfloat16 *whi, *wlo;
    cudaGetSymbolAddress((void**)&agg1,   g_agg1);
    cudaGetSymbolAddress((void**)&h,      g_h);
    cudaGetSymbolAddress((void**)&agg2,   g_agg2);
    cudaGetSymbolAddress((void**)&h2,     g_h2);
    cudaGetSymbolAddress((void**)&t1,     g_t1);
    cudaGetSymbolAddress((void**)&pooled, g_pooled);
    cudaGetSymbolAddress((void**)&whi,    g_whi);
    cudaGetSymbolAddress((void**)&wlo,    g_wlo);

    // matrix order in whi/wlo: 0=c1_w2, 1=c2_w1, 2=c2_w2, 3=n_w1, 4=n_w2
    __nv_bfloat16* whi_c1w2 = whi;
    __nv_bfloat16* whi_c2w1 = whi + 16384;
    __nv_bfloat16* whi_c2w2 = whi + 2 * 16384;
    __nv_bfloat16* whi_nw1  = whi + 3 * 16384;
    __nv_bfloat16* whi_nw2  = whi + 4 * 16384;
    __nv_bfloat16* wlo_c1w2 = wlo;
    __nv_bfloat16* wlo_c2w1 = wlo + 16384;
    __nv_bfloat16* wlo_c2w2 = wlo + 2 * 16384;
    __nv_bfloat16* wlo_nw1  = wlo + 3 * 16384;
    __nv_bfloat16* wlo_nw2  = wlo + 4 * 16384;

    float* out = (float*)d_out;

    // aHi+aLo+bHi+bLo+bias = 17408*2 + 34816*2 + 8448 = 112896 B -> 2 CTAs/SM
    const int WM_SMEM = 112896;
    cudaFuncSetAttribute(wmma_gemm<0, false>, cudaFuncAttributeMaxDynamicSharedMemorySize, WM_SMEM);
    cudaFuncSetAttribute(wmma_gemm<0, true >, cudaFuncAttributeMaxDynamicSharedMemorySize, WM_SMEM);
    cudaFuncSetAttribute(wmma_gemm<1, false>, cudaFuncAttributeMaxDynamicSharedMemorySize, WM_SMEM);

    // launches 0,1: memsets
    cudaMemsetAsync(agg1, 0, (size_t)N * 32 * sizeof(float));
    cudaMemsetAsync(agg2, 0, (size_t)N * HD * sizeof(float));

    // launch 2: single combined weight split
    wsplit_all<<<dim3(64, 5), 256>>>(c1_w2, c2_w1, c2_w2, n_w1, n_w2, whi, wlo);

    int mgrid = N / 64;

    // launch 3,4: GINE layer 1 edge + K=32 GEMM
    edge1_kernel<<<(E / E1_CHUNK + 7) / 8, 256>>>(x, src, dst, ea, e1_w, e1_b, agg1, E);
    gemm_kernel<32, 0, true><<<N / 64, 256>>>(x, agg1, c1_w1, c1_b1, t1);
    // launch 5: FIRST wmma GEMM  <-- ncu -s 5 profiles this
    wmma_gemm<1, false><<<mgrid, 256, WM_SMEM>>>(t1, t1, whi_c1w2, wlo_c1w2, c1_b2, h);  // relu

    // GINE layer 2
    edge2_kernel<<<(2 * (E / E2_CHUNK) + 7) / 8, 256>>>(h, src, dst, ea, e2_w, e2_b, agg2, E);
    wmma_gemm<0, true ><<<mgrid, 256, WM_SMEM>>>(h, agg2, whi_c2w1, wlo_c2w1, c2_b1, t1);
    wmma_gemm<0, false><<<mgrid, 256, WM_SMEM>>>(t1, t1, whi_c2w2, wlo_c2w2, c2_b2, h2);

    // Action head
    pool_kernel<<<64, 256>>>(h2, pooled, Nper);
    action_kernel<<<64, 128>>>(pooled, a_w1, a_b1, a_w2, a_b2, out);

    // Node score head (reuse agg2 as nh2)
    wmma_gemm<0, false><<<mgrid, 256, WM_SMEM>>>(h2, h2, whi_nw1, wlo_nw1, n_b1, t1);
    wmma_gemm<0, false><<<mgrid, 256, WM_SMEM>>>(t1, t1, whi_nw2, wlo_nw2, n_b2, agg2);
    score_kernel<<<(N + 7) / 8, 256>>>(agg2, n_w3, n_b3, out + 640, N, Nper);
}

// round 11
// speedup vs baseline: 1.3888x; 1.3888x over previous
#include <cuda_runtime.h>
#include <math.h>
#include <stdint.h>

#define NMAX 65536
#define HD   128

typedef unsigned long long u64;

// ----- scratch -----
__device__ float g_agg1[NMAX * 32];
__device__ float g_h   [NMAX * HD];
__device__ float g_agg2[NMAX * HD];   // reused as nh2 at the end
__device__ float g_h2  [NMAX * HD];
__device__ float g_t1  [NMAX * HD];
__device__ float g_pooled[64 * HD];

__device__ __forceinline__ float leakyf(float v) { return v > 0.f ? v : 0.01f * v; }

__device__ __forceinline__ u64 pack2(float lo, float hi) {
    u64 r; asm("mov.b64 %0, {%1, %2};" : "=l"(r) : "f"(lo), "f"(hi)); return r;
}
__device__ __forceinline__ void unpack2(float& lo, float& hi, u64 v) {
    asm("mov.b64 {%0, %1}, %2;" : "=f"(lo), "=f"(hi) : "l"(v));
}
__device__ __forceinline__ u64 fma2(u64 a, u64 b, u64 c) {
    u64 d; asm("fma.rn.f32x2 %0, %1, %2, %3;" : "=l"(d) : "l"(a), "l"(b), "l"(c)); return d;
}

// ---------------------------------------------------------------------------
// f32x2 GEMM, K=128: Out[N,128] = act( (In (+In2)) @ W[128,128] + bias )
// 256 threads; 128x128 tile; per-thread 8 rows x 8 cols; k-pair LDS.64 loads.
// smem: sIn 64KB + sW 8KB (dynamic) -> 2 CTAs/SM. ACT: 0=leaky, 1=relu
// ---------------------------------------------------------------------------
template<int ACT, bool ADD>
__global__ __launch_bounds__(256, 2)
void gemm128_kernel(const float* __restrict__ In, const float* __restrict__ In2,
                    const float* __restrict__ W, const float* __restrict__ bias,
                    float* __restrict__ Out)
{
    extern __shared__ __align__(16) float smem_f[];
    float* sIn = smem_f;            // 128*128 = 16384 floats (64KB)
    float* sW  = smem_f + 16384;    // 16*128  = 2048 floats  (8KB)

    int tid = threadIdx.x;
    int row0 = blockIdx.x * 128;

    // ---- prologue: load A tile (optionally fused add)
    const float4* inp  = (const float4*)(In  + (size_t)row0 * 128);
    const float4* inp2 = (const float4*)(In2 + (size_t)row0 * 128);
    #pragma unroll
    for (int it = 0; it < 16; it++) {
        int i = it * 256 + tid;
        float4 v = inp[i];
        if (ADD) { float4 u = inp2[i]; v.x += u.x; v.y += u.y; v.z += u.z; v.w += u.w; }
        ((float4*)sIn)[i] = v;
    }

    int cx = tid & 15;       // cols cx*8 .. +7
    int ry = tid >> 4;       // rows ry*8 .. +7
    int c0 = cx * 8;

    u64 acc[8][4];
    {
        u64 b[4];
        #pragma unroll
        for (int j = 0; j < 4; j++) {
            float2 t = *(const float2*)(bias + c0 + 2 * j);
            b[j] = pack2(t.x, t.y);
        }
        #pragma unroll
        for (int r = 0; r < 8; r++)
            #pragma unroll
            for (int j = 0; j < 4; j++) acc[r][j] = b[j];
    }

    for (int kc = 0; kc < 128; kc += 16) {
        __syncthreads();
        #pragma unroll
        for (int it = 0; it < 2; it++) {
            int i = it * 256 + tid;
            ((float4*)sW)[i] = ((const float4*)(W + (size_t)kc * 128))[i];
        }
        __syncthreads();
        #pragma unroll
        for (int k2 = 0; k2 < 16; k2 += 2) {
            u64 w0[4], w1[4];
            #pragma unroll
            for (int j = 0; j < 4; j++) {
                w0[j] = *(const u64*)(sW + k2 * 128 + c0 + 2 * j);
                w1[j] = *(const u64*)(sW + (k2 + 1) * 128 + c0 + 2 * j);
            }
            #pragma unroll
            for (int r = 0; r < 8; r++) {
                float2 a2 = *(const float2*)(sIn + (ry * 8 + r) * 128 + kc + k2);
                u64 aa0 = pack2(a2.x, a2.x);
                u64 aa1 = pack2(a2.y, a2.y);
                #pragma unroll
                for (int j = 0; j < 4; j++) {
                    acc[r][j] = fma2(aa0, w0[j], acc[r][j]);
                    acc[r][j] = fma2(aa1, w1[j], acc[r][j]);
                }
            }
        }
    }

    // ---- epilogue
    #pragma unroll
    for (int r = 0; r < 8; r++) {
        float o[8];
        #pragma unroll
        for (int j = 0; j < 4; j++) unpack2(o[2 * j], o[2 * j + 1], acc[r][j]);
        #pragma unroll
        for (int j = 0; j < 8; j++) o[j] = (ACT == 0) ? leakyf(o[j]) : fmaxf(o[j], 0.f);
        float4* orow = (float4*)(Out + (size_t)(row0 + ry * 8 + r) * 128 + c0);
        orow[0] = make_float4(o[0], o[1], o[2], o[3]);
        orow[1] = make_float4(o[4], o[5], o[6], o[7]);
    }
}

// ---------------------------------------------------------------------------
// Edge layer 1 (R5, unchanged)
// ---------------------------------------------------------------------------
#define E1_CHUNK 32
__global__ __launch_bounds__(256)
void edge1_kernel(const float* __restrict__ x, const int* __restrict__ src,
                  const int* __restrict__ dst, const float* __restrict__ ea,
                  const float* __restrict__ W, const float* __restrict__ bias,
                  float* __restrict__ agg, int E)
{
    int lane = threadIdx.x & 31;
    int warp = blockIdx.x * 8 + (threadIdx.x >> 5);
    int base = warp * E1_CHUNK;
    if (base >= E) return;

    float w[16];
    #pragma unroll
    for (int k = 0; k < 16; k++) w[k] = __ldg(&W[k * 32 + lane]);
    float b = __ldg(&bias[lane]);

    int sA = __ldg(&src[base + lane]);
    int sD = __ldg(&dst[base + lane]);

    #pragma unroll 4
    for (int i = 0; i < E1_CHUNK; i++) {
        int e = base + i;
        int s = __shfl_sync(0xffffffffu, sA, i);
        int d = __shfl_sync(0xffffffffu, sD, i);
        float av = (lane < 16) ? __ldg(&ea[(size_t)e * 16 + lane]) : 0.f;
        float g = __ldg(&x[(size_t)s * 32 + lane]);
        float t = b;
        #pragma unroll
        for (int k = 0; k < 16; k++)
            t = fmaf(__shfl_sync(0xffffffffu, av, k), w[k], t);
        float m = fmaxf(t + g, 0.f);
        asm volatile("red.global.add.f32 [%0], %1;"
                     :: "l"(agg + (size_t)d * 32 + lane), "f"(m) : "memory");
    }
}

// ---------------------------------------------------------------------------
// Edge layer 2 (R5, unchanged): two warps / 16-edge chunk, 64 ch per warp
// ---------------------------------------------------------------------------
#define E2_CHUNK 16
__global__ __launch_bounds__(256, 4)
void edge2_kernel(const float* __restrict__ h, const int* __restrict__ src,
                  const int* __restrict__ dst, const float* __restrict__ ea,
                  const float* __restrict__ W, const float* __restrict__ bias,
                  float* __restrict__ agg, int E)
{
    int lane = threadIdx.x & 31;
    int warp = blockIdx.x * 8 + (threadIdx.x >> 5);
    int chunk = warp >> 1;
    int half  = warp & 1;
    int base = chunk * E2_CHUNK;
    if (base >= E) return;
    int ch = half * 64 + lane * 2;

    u64 w2[16];
    #pragma unroll
    for (int k = 0; k < 16; k++) {
        float2 wv = *(const float2*)(W + (size_t)k * 128 + ch);
        w2[k] = pack2(wv.x, wv.y);
    }
    float2 bv = *(const float2*)(bias + ch);
    u64 b2 = pack2(bv.x, bv.y);

    int li = lane & 15;
    int sd = (lane < 16) ? __ldg(&src[base + li]) : __ldg(&dst[base + li]);

    for (int i = 0; i < E2_CHUNK; i++) {
        int e = base + i;
        int s = __shfl_sync(0xffffffffu, sd, i);
        int d = __shfl_sync(0xffffffffu, sd, 16 + i);
        float av = (lane < 16) ? __ldg(&ea[(size_t)e * 16 + lane]) : 0.f;
        float2 g = *(const float2*)(h + (size_t)s * HD + ch);

        u64 tE = b2, tO = 0ull;
        #pragma unroll
        for (int k = 0; k < 16; k += 2) {
            float a0 = __shfl_sync(0xffffffffu, av, k);
            float a1 = __shfl_sync(0xffffffffu, av, k + 1);
            tE = fma2(pack2(a0, a0), w2[k],     tE);
            tO = fma2(pack2(a1, a1), w2[k + 1], tO);
        }
        float tx, ty, ux, uy;
        unpack2(tx, ty, tE);
        unpack2(ux, uy, tO);
        float mx = fmaxf(tx + ux + g.x, 0.f);
        float my = fmaxf(ty + uy + g.y, 0.f);
        asm volatile("red.global.add.v2.f32 [%0], {%1,%2};"
                     :: "l"(agg + (size_t)d * HD + ch), "f"(mx), "f"(my) : "memory");
    }
}

// ---------------------------------------------------------------------------
// FFMA GEMM for the K=32 layer (R5, unchanged)
// ---------------------------------------------------------------------------
template<int K, int ACT, bool ADD>
__global__ __launch_bounds__(256)
void gemm_kernel(const float* __restrict__ In, const float* __restrict__ In2,
                 const float* __restrict__ W, const float* __restrict__ bias,
                 float* __restrict__ Out)
{
    __shared__ float sIn[64 * K];
    __shared__ float sW[16 * 128];
    int tid = threadIdx.x;
    int row0 = blockIdx.x * 64;

    const float4* inp  = (const float4*)(In  + (size_t)row0 * K);
    const float4* inp2 = (const float4*)(In2 + (size_t)row0 * K);
    for (int i = tid; i < (64 * K) / 4; i += 256) {
        float4 v = inp[i];
        if (ADD) {
            float4 u = inp2[i];
            v.x += u.x; v.y += u.y; v.z += u.z; v.w += u.w;
        }
        ((float4*)sIn)[i] = v;
    }

    int cx = tid & 31;
    int ry = tid >> 5;
    float4 b4 = ((const float4*)bias)[cx];
    float4 acc[8];
    #pragma unroll
    for (int m = 0; m < 8; m++) acc[m] = b4;

    for (int kc = 0; kc < K; kc += 16) {
        __syncthreads();
        for (int i = tid; i < (16 * 128) / 4; i += 256)
            ((float4*)sW)[i] = ((const float4*)(W + (size_t)kc * 128))[i];
        __syncthreads();
        #pragma unroll
        for (int k = 0; k < 16; k++) {
            float4 w = ((float4*)sW)[k * 32 + cx];
            #pragma unroll
            for (int m = 0; m < 8; m++) {
                float a = sIn[(ry * 8 + m) * K + (kc + k)];
                acc[m].x += a * w.x; acc[m].y += a * w.y;
                acc[m].z += a * w.z; acc[m].w += a * w.w;
            }
        }
    }

    #pragma unroll
    for (int m = 0; m < 8; m++) {
        float4 v = acc[m];
        if (ACT == 0) {
            v.x = leakyf(v.x); v.y = leakyf(v.y); v.z = leakyf(v.z); v.w = leakyf(v.w);
        } else {
            v.x = fmaxf(v.x, 0.f); v.y = fmaxf(v.y, 0.f);
            v.z = fmaxf(v.z, 0.f); v.w = fmaxf(v.w, 0.f);
        }
        *(float4*)(Out + (size_t)(row0 + ry * 8 + m) * 128 + cx * 4) = v;
    }
}

// ---------------------------------------------------------------------------
__global__ void pool_kernel(const float* __restrict__ h2, float* __restrict__ pooled, int Nper)
{
    int b = blockIdx.x;
    int tid = threadIdx.x;
    int c = tid & 127, half = tid >> 7;
    float s = 0.f;
    const float* base = h2 + (size_t)b * Nper * HD + c;
    for (int i = half; i < Nper; i += 2) s += base[(size_t)i * HD];
    __shared__ float sm[256];
    sm[tid] = s;
    __syncthreads();
    if (half == 0) pooled[b * HD + c] = (sm[c] + sm[128 + c]) / (float)Nper;
}

__global__ void action_kernel(const float* __restrict__ pooled,
                              const float* __restrict__ w1, const float* __restrict__ b1,
                              const float* __restrict__ w2, const float* __restrict__ b2,
                              float* __restrict__ out)
{
    __shared__ float sp[128], s1[128], s2[10];
    int b = blockIdx.x;
    int tid = threadIdx.x;
    sp[tid] = pooled[b * 128 + tid];
    __syncthreads();
    float acc = b1[tid];
    #pragma unroll 8
    for (int k = 0; k < 128; k++) acc += sp[k] * w1[k * 128 + tid];
    s1[tid] = leakyf(acc);
    __syncthreads();
    if (tid < 10) {
        float a2 = b2[tid];
        #pragma unroll 8
        for (int k = 0; k < 128; k++) a2 += s1[k] * w2[k * 10 + tid];
        s2[tid] = leakyf(a2);
    }
    __syncthreads();
    if (tid == 0) {
        float mx = -1e30f;
        for (int j = 0; j < 10; j++) mx = fmaxf(mx, s2[j]);
        float ex[10], sum = 0.f;
        for (int j = 0; j < 10; j++) { ex[j] = expf(s2[j] - mx); sum += ex[j]; }
        float inv = 1.f / sum;
        for (int j = 0; j < 10; j++) out[b * 10 + j] = ex[j] * inv;
    }
}

__global__ void score_kernel(const float* __restrict__ nh, const float* __restrict__ w3,
                             const float* __restrict__ b3, float* __restrict__ out,
                             int N, int Nper)
{
    int r = blockIdx.x * 8 + (threadIdx.x >> 5);
    int lane = threadIdx.x & 31;
    if (r >= N) return;
    float4 v = *(const float4*)(nh + (size_t)r * HD + lane * 4);
    float4 w = *(const float4*)(w3 + lane * 4);
    float acc = v.x * w.x + v.y * w.y + v.z * w.z + v.w * w.w;
    #pragma unroll
    for (int o = 16; o; o >>= 1) acc += __shfl_xor_sync(0xffffffffu, acc, o);
    if (lane == 0) {
        float z = acc + b3[0];
        out[(size_t)(r & 63) * Nper + (r >> 6)] = 1.f / (1.f + expf(-z));
    }
}

// ---------------------------------------------------------------------------
extern "C" void kernel_launch(void* const* d_in, const int* in_sizes, int n_in,
                              void* d_out, int out_size)
{
    const float* x     = (const float*)d_in[0];
    const int*   ei    = (const int*)  d_in[1];
    const float* ea    = (const float*)d_in[2];
    const float* e1_w  = (const float*)d_in[3];
    const float* e1_b  = (const float*)d_in[4];
    const float* c1_w1 = (const float*)d_in[5];
    const float* c1_b1 = (const float*)d_in[6];
    const float* c1_w2 = (const float*)d_in[7];
    const float* c1_b2 = (const float*)d_in[8];
    const float* e2_w  = (const float*)d_in[9];
    const float* e2_b  = (const float*)d_in[10];
    const float* c2_w1 = (const float*)d_in[11];
    const float* c2_b1 = (const float*)d_in[12];
    const float* c2_w2 = (const float*)d_in[13];
    const float* c2_b2 = (const float*)d_in[14];
    const float* a_w1  = (const float*)d_in[15];
    const float* a_b1  = (const float*)d_in[16];
    const float* a_w2  = (const float*)d_in[17];
    const float* a_b2  = (const float*)d_in[18];
    const float* n_w1  = (const float*)d_in[19];
    const float* n_b1  = (const float*)d_in[20];
    const float* n_w2  = (const float*)d_in[21];
    const float* n_b2  = (const float*)d_in[22];
    const float* n_w3  = (const float*)d_in[23];
    const float* n_b3  = (const float*)d_in[24];

    int N = in_sizes[0] / 32;
    int E = in_sizes[1] / 2;
    int Nper = N / 64;
    const int* src = ei;
    const int* dst = ei + E;

    float *agg1, *h, *agg2, *h2, *t1, *pooled;
    cudaGetSymbolAddress((void**)&agg1,   g_agg1);
    cudaGetSymbolAddress((void**)&h,      g_h);
    cudaGetSymbolAddress((void**)&agg2,   g_agg2);
    cudaGetSymbolAddress((void**)&h2,     g_h2);
    cudaGetSymbolAddress((void**)&t1,     g_t1);
    cudaGetSymbolAddress((void**)&pooled, g_pooled);

    float* out = (float*)d_out;

    const int G128_SMEM = (16384 + 2048) * 4;   // 73728 B
    cudaFuncSetAttribute(gemm128_kernel<0, false>, cudaFuncAttributeMaxDynamicSharedMemorySize, G128_SMEM);
    cudaFuncSetAttribute(gemm128_kernel<0, true >, cudaFuncAttributeMaxDynamicSharedMemorySize, G128_SMEM);
    cudaFuncSetAttribute(gemm128_kernel<1, false>, cudaFuncAttributeMaxDynamicSharedMemorySize, G128_SMEM);

    // launches 0,1: memsets
    cudaMemsetAsync(agg1, 0, (size_t)N * 32 * sizeof(float));
    cudaMemsetAsync(agg2, 0, (size_t)N * HD * sizeof(float));

    int mgrid = N / 128;
    int halfN = N / 2;

    // launch 2: edge1 ; 3,4: K=32 GEMM split in two (so launch 5 = gemm128)
    edge1_kernel<<<(E / E1_CHUNK + 7) / 8, 256>>>(x, src, dst, ea, e1_w, e1_b, agg1, E);
    gemm_kernel<32, 0, true><<<halfN / 64, 256>>>(x, agg1, c1_w1, c1_b1, t1);
    gemm_kernel<32, 0, true><<<halfN / 64, 256>>>(x + (size_t)halfN * 32, agg1 + (size_t)halfN * 32,
                                                  c1_w1, c1_b1, t1 + (size_t)halfN * 128);
    // launch 5: first f32x2 K=128 GEMM  <-- ncu -s 5 profiles this
    gemm128_kernel<1, false><<<mgrid, 256, G128_SMEM>>>(t1, t1, c1_w2, c1_b2, h);   // relu

    // GINE layer 2
    edge2_kernel<<<(2 * (E / E2_CHUNK) + 7) / 8, 256>>>(h, src, dst, ea, e2_w, e2_b, agg2, E);
    gemm128_kernel<0, true ><<<mgrid, 256, G128_SMEM>>>(h, agg2, c2_w1, c2_b1, t1);
    gemm128_kernel<0, false><<<mgrid, 256, G128_SMEM>>>(t1, t1, c2_w2, c2_b2, h2);

    // Action head
    pool_kernel<<<64, 256>>>(h2, pooled, Nper);
    action_kernel<<<64, 128>>>(pooled, a_w1, a_b1, a_w2, a_b2, out);

    // Node score head (reuse agg2 as nh2)
    gemm128_kernel<0, false><<<mgrid, 256, G128_SMEM>>>(h2, h2, n_w1, n_b1, t1);
    gemm128_kernel<0, false><<<mgrid, 256, G128_SMEM>>>(t1, t1, n_w2, n_b2, agg2);
    score_kernel<<<(N + 7) / 8, 256>>>(agg2, n_w3, n_b3, out + 640, N, Nper);
}